// round 3
// baseline (speedup 1.0000x reference)
#include <cuda_runtime.h>
#include <math.h>

// ---------------- problem constants ----------------
#define N_NODES 50000
#define N_EDGES 600000

// ---------------- scratch (no allocations allowed) ----------------
__device__ float g_B1[(size_t)N_NODES * 128];  // [N,128] buffer (AGGX, H2raw, H3)
__device__ float g_B2[(size_t)N_NODES * 256];  // [N,256] buffer (H1, AGG2/h2)
__device__ float g_deg[N_NODES];
__device__ float g_dinv[N_NODES];

// ---------------- degree / normalization ----------------
__global__ void k_deg_init(float* deg) {
    int i = blockIdx.x * blockDim.x + threadIdx.x;
    if (i < N_NODES) deg[i] = 1.0f;  // self-loop
}

__global__ void k_deg_count(float* deg, const int* __restrict__ ei) {
    int e = blockIdx.x * blockDim.x + threadIdx.x;
    if (e < N_EDGES) {
        int d = ei[N_EDGES + e];  // dst row
        atomicAdd(&deg[d], 1.0f);
    }
}

__global__ void k_dinv(const float* __restrict__ deg, float* dinv) {
    int i = blockIdx.x * blockDim.x + threadIdx.x;
    if (i < N_NODES) dinv[i] = rsqrtf(deg[i]);
}

// ---------------- aggregation helpers ----------------
// AGG[i,c] = H[i,c] * dinv[i]^2  (self-loop term), vectorized float4
__global__ void k_agg_init(const float* __restrict__ H, float* __restrict__ AGG,
                           const float* __restrict__ dinv, int total4, int C) {
    int idx = blockIdx.x * blockDim.x + threadIdx.x;
    if (idx >= total4) return;
    int node = (idx * 4) / C;
    float dv = dinv[node];
    float s = dv * dv;
    float4 v = ((const float4*)H)[idx];
    v.x *= s; v.y *= s; v.z *= s; v.w *= s;
    ((float4*)AGG)[idx] = v;
}

// one warp per edge, 128 channels (32 lanes x float4)
__global__ void k_scatter128(const float* __restrict__ H, float* __restrict__ AGG,
                             const int* __restrict__ ei,
                             const float* __restrict__ dinv) {
    int gt = blockIdx.x * blockDim.x + threadIdx.x;
    int e = gt >> 5;
    int lane = gt & 31;
    if (e >= N_EDGES) return;
    int s = ei[e];             // same-address warp load -> broadcast
    int d = ei[N_EDGES + e];
    float nrm = dinv[s] * dinv[d];
    float4 v = *(const float4*)(H + (size_t)s * 128 + lane * 4);
    float* out = AGG + (size_t)d * 128 + lane * 4;
    atomicAdd(out + 0, v.x * nrm);
    atomicAdd(out + 1, v.y * nrm);
    atomicAdd(out + 2, v.z * nrm);
    atomicAdd(out + 3, v.w * nrm);
}

// A[i,c] = relu(A[i,c] + bias[c]), vectorized
__global__ void k_bias_relu(float* __restrict__ A, const float* __restrict__ bias,
                            int total4, int C) {
    int idx = blockIdx.x * blockDim.x + threadIdx.x;
    if (idx >= total4) return;
    int col = (idx * 4) % C;
    float4 b = *(const float4*)(bias + col);
    float4 v = ((float4*)A)[idx];
    v.x = fmaxf(v.x + b.x, 0.0f);
    v.y = fmaxf(v.y + b.y, 0.0f);
    v.z = fmaxf(v.z + b.z, 0.0f);
    v.w = fmaxf(v.w + b.w, 0.0f);
    ((float4*)A)[idx] = v;
}

// ---------------- SGEMM: C[M,N] = A[M,K] @ B[K,N] (+bias, relu) ----------------
// BM=BN=64, BK=16, 256 threads, 4x4 register tile. N % 64 == 0, K % 16 == 0.
#define BM 64
#define BN 64
#define BKT 16
__global__ __launch_bounds__(256) void k_sgemm(const float* __restrict__ A,
                                               const float* __restrict__ B,
                                               float* __restrict__ C,
                                               int M, int K, int N,
                                               const float* __restrict__ bias,
                                               int do_relu) {
    __shared__ float As[BKT][BM];
    __shared__ float Bs[BKT][BN];

    int tid = threadIdx.x;
    int tx = tid & 15;        // col group 0..15
    int ty = tid >> 4;        // row group 0..15
    int rowBase = blockIdx.y * BM;
    int colBase = blockIdx.x * BN;

    // load mapping
    int aRow  = tid >> 2;            // 0..63
    int aCol4 = (tid & 3) * 4;       // 0,4,8,12
    int bRow  = tid >> 4;            // 0..15
    int bCol4 = (tid & 15) * 4;      // 0..60

    float acc[4][4];
#pragma unroll
    for (int i = 0; i < 4; i++)
#pragma unroll
        for (int j = 0; j < 4; j++) acc[i][j] = 0.0f;

    for (int k0 = 0; k0 < K; k0 += BKT) {
        float4 av = make_float4(0.f, 0.f, 0.f, 0.f);
        int gr = rowBase + aRow;
        if (gr < M) av = *(const float4*)(A + (size_t)gr * K + k0 + aCol4);
        As[aCol4 + 0][aRow] = av.x;
        As[aCol4 + 1][aRow] = av.y;
        As[aCol4 + 2][aRow] = av.z;
        As[aCol4 + 3][aRow] = av.w;

        float4 bv = *(const float4*)(B + (size_t)(k0 + bRow) * N + colBase + bCol4);
        Bs[bRow][bCol4 + 0] = bv.x;
        Bs[bRow][bCol4 + 1] = bv.y;
        Bs[bRow][bCol4 + 2] = bv.z;
        Bs[bRow][bCol4 + 3] = bv.w;
        __syncthreads();

#pragma unroll
        for (int k = 0; k < BKT; k++) {
            float ra[4], rb[4];
#pragma unroll
            for (int i = 0; i < 4; i++) ra[i] = As[k][ty * 4 + i];
#pragma unroll
            for (int j = 0; j < 4; j++) rb[j] = Bs[k][tx * 4 + j];
#pragma unroll
            for (int i = 0; i < 4; i++)
#pragma unroll
                for (int j = 0; j < 4; j++) acc[i][j] += ra[i] * rb[j];
        }
        __syncthreads();
    }

#pragma unroll
    for (int i = 0; i < 4; i++) {
        int row = rowBase + ty * 4 + i;
        if (row >= M) continue;
#pragma unroll
        for (int j = 0; j < 4; j++) {
            int col = colBase + tx * 4 + j;
            float v = acc[i][j];
            if (bias) v += bias[col];
            if (do_relu) v = fmaxf(v, 0.0f);
            C[(size_t)row * N + col] = v;
        }
    }
}

// ---------------- layer 3: H3[N,2] = h2[N,128] @ W3[128,2] ----------------
__global__ void k_gemm_small(const float* __restrict__ H2, const float* __restrict__ W3,
                             float* __restrict__ H3) {
    __shared__ float w[256];
    if (threadIdx.x < 256) w[threadIdx.x] = W3[threadIdx.x];
    __syncthreads();
    int r = blockIdx.x * blockDim.x + threadIdx.x;
    if (r >= N_NODES) return;
    float a0 = 0.f, a1 = 0.f;
    const float4* row = (const float4*)(H2 + (size_t)r * 128);
#pragma unroll
    for (int k = 0; k < 32; k++) {
        float4 v = row[k];
        int b = k * 8;  // (4k)*2
        a0 += v.x * w[b + 0] + v.y * w[b + 2] + v.z * w[b + 4] + v.w * w[b + 6];
        a1 += v.x * w[b + 1] + v.y * w[b + 3] + v.z * w[b + 5] + v.w * w[b + 7];
    }
    H3[(size_t)r * 2 + 0] = a0;
    H3[(size_t)r * 2 + 1] = a1;
}

__global__ void k_agg_init2(const float* __restrict__ H3, float* __restrict__ AGG,
                            const float* __restrict__ dinv) {
    int i = blockIdx.x * blockDim.x + threadIdx.x;
    if (i >= N_NODES) return;
    float dv = dinv[i];
    float s = dv * dv;
    float2 v = *(const float2*)(H3 + (size_t)i * 2);
    v.x *= s; v.y *= s;
    *(float2*)(AGG + (size_t)i * 2) = v;
}

__global__ void k_scatter2(const float* __restrict__ H3, float* __restrict__ AGG,
                           const int* __restrict__ ei,
                           const float* __restrict__ dinv) {
    int e = blockIdx.x * blockDim.x + threadIdx.x;
    if (e >= N_EDGES) return;
    int s = ei[e];
    int d = ei[N_EDGES + e];
    float nrm = dinv[s] * dinv[d];
    float2 v = *(const float2*)(H3 + (size_t)s * 2);
    atomicAdd(AGG + (size_t)d * 2 + 0, v.x * nrm);
    atomicAdd(AGG + (size_t)d * 2 + 1, v.y * nrm);
}

__global__ void k_log_softmax(float* __restrict__ out, const float* __restrict__ b3) {
    int i = blockIdx.x * blockDim.x + threadIdx.x;
    if (i >= N_NODES) return;
    float v0 = out[(size_t)i * 2 + 0] + b3[0];
    float v1 = out[(size_t)i * 2 + 1] + b3[1];
    float m = fmaxf(v0, v1);
    float lse = m + logf(expf(v0 - m) + expf(v1 - m));
    out[(size_t)i * 2 + 0] = v0 - lse;
    out[(size_t)i * 2 + 1] = v1 - lse;
}

// ---------------- launch ----------------
extern "C" void kernel_launch(void* const* d_in, const int* in_sizes, int n_in,
                              void* d_out, int out_size) {
    const float* x  = (const float*)d_in[0];
    const float* W1 = (const float*)d_in[1];
    const float* b1 = (const float*)d_in[2];
    const float* W2 = (const float*)d_in[3];
    const float* b2 = (const float*)d_in[4];
    const float* W3 = (const float*)d_in[5];
    const float* b3 = (const float*)d_in[6];
    const int*   ei = (const int*)d_in[7];   // int32: JAX x64 disabled
    float* out = (float*)d_out;

    float *B1, *B2, *deg, *dinv;
    cudaGetSymbolAddress((void**)&B1, g_B1);
    cudaGetSymbolAddress((void**)&B2, g_B2);
    cudaGetSymbolAddress((void**)&deg, g_deg);
    cudaGetSymbolAddress((void**)&dinv, g_dinv);

    const int N = N_NODES, E = N_EDGES;
    const int TB = 256;

    // degree + dinv
    k_deg_init<<<(N + TB - 1) / TB, TB>>>(deg);
    k_deg_count<<<(E + TB - 1) / TB, TB>>>(deg, ei);
    k_dinv<<<(N + TB - 1) / TB, TB>>>(deg, dinv);

    // layer 1: aggregate input first (A@x), then dense: B2 = relu((A@x)@W1 + b1)
    {
        int total4 = N * 128 / 4;
        k_agg_init<<<(total4 + TB - 1) / TB, TB>>>(x, B1, dinv, total4, 128);
        long long thr = (long long)E * 32;
        k_scatter128<<<(int)((thr + TB - 1) / TB), TB>>>(x, B1, ei, dinv);
        dim3 g1(256 / BN, (N + BM - 1) / BM);
        k_sgemm<<<g1, 256>>>(B1, W1, B2, N, 128, 256, b1, 1);
    }

    // layer 2: H2 = h1@W2 -> B1 [N,128]; aggregate -> B2; relu(+b2)
    {
        dim3 g2(128 / BN, (N + BM - 1) / BM);
        k_sgemm<<<g2, 256>>>(B2, W2, B1, N, 256, 128, nullptr, 0);
        int total4 = N * 128 / 4;
        k_agg_init<<<(total4 + TB - 1) / TB, TB>>>(B1, B2, dinv, total4, 128);
        long long thr = (long long)E * 32;
        k_scatter128<<<(int)((thr + TB - 1) / TB), TB>>>(B1, B2, ei, dinv);
        k_bias_relu<<<(total4 + TB - 1) / TB, TB>>>(B2, b2, total4, 128);
    }

    // layer 3: H3 = h2@W3 -> B1 [N,2]; aggregate into d_out; +b3; log_softmax
    {
        k_gemm_small<<<(N + TB - 1) / TB, TB>>>(B2, W3, B1);
        k_agg_init2<<<(N + TB - 1) / TB, TB>>>(B1, out, dinv);
        k_scatter2<<<(E + TB - 1) / TB, TB>>>(B1, out, ei, dinv);
        k_log_softmax<<<(N + TB - 1) / TB, TB>>>(out, b3);
    }
}

// round 4
// speedup vs baseline: 1.9457x; 1.9457x over previous
#include <cuda_runtime.h>
#include <math.h>

// ---------------- problem constants ----------------
#define N_NODES 50000
#define N_EDGES 600000

// ---------------- scratch (no allocations allowed) ----------------
__device__ float g_B1[(size_t)N_NODES * 128];   // [N,128] buffer
__device__ float g_B2[(size_t)N_NODES * 256];   // [N,256] buffer
__device__ float g_dinv[N_NODES];
__device__ int   g_indptr[N_NODES + 1];
__device__ int   g_cursor[N_NODES];             // counts, then fill cursor
__device__ int   g_srcs[N_EDGES];
__device__ int   g_blocksums[128];

// ================= CSR build =================
__global__ void k_zero(int* cursor) {
    int i = blockIdx.x * blockDim.x + threadIdx.x;
    if (i < N_NODES) cursor[i] = 0;
}

__global__ void k_count(int* cursor, const int* __restrict__ ei) {
    int e = blockIdx.x * blockDim.x + threadIdx.x;
    if (e < N_EDGES) atomicAdd(&cursor[ei[N_EDGES + e]], 1);
}

// per-block inclusive scan of 512 counts -> exclusive indptr (local), dinv
__global__ void k_scan1(const int* __restrict__ counts, int* indptr,
                        int* blocksums, float* dinv) {
    __shared__ int sm[512];
    int i = blockIdx.x * 512 + threadIdx.x;
    int c = (i < N_NODES) ? counts[i] : 0;
    if (i < N_NODES) dinv[i] = rsqrtf((float)(c + 1));  // +1 self loop
    sm[threadIdx.x] = c;
    __syncthreads();
#pragma unroll
    for (int off = 1; off < 512; off <<= 1) {
        int v = (threadIdx.x >= off) ? sm[threadIdx.x - off] : 0;
        __syncthreads();
        sm[threadIdx.x] += v;
        __syncthreads();
    }
    if (i < N_NODES) indptr[i] = sm[threadIdx.x] - c;  // exclusive
    if (threadIdx.x == 511) blocksums[blockIdx.x] = sm[511];
}

__global__ void k_scan2(int* blocksums, int nb) {
    __shared__ int sm[128];
    int t = threadIdx.x;
    int v = (t < nb) ? blocksums[t] : 0;
    sm[t] = v;
    __syncthreads();
#pragma unroll
    for (int off = 1; off < 128; off <<= 1) {
        int u = (t >= off) ? sm[t - off] : 0;
        __syncthreads();
        sm[t] += u;
        __syncthreads();
    }
    if (t < nb) blocksums[t] = sm[t] - v;  // exclusive block offsets
}

__global__ void k_scan3(int* indptr, const int* __restrict__ blocksums, int* cursor) {
    int i = blockIdx.x * blockDim.x + threadIdx.x;
    if (i < N_NODES) {
        indptr[i] += blocksums[i >> 9];
        cursor[i] = 0;
    }
    if (i == 0) indptr[N_NODES] = N_EDGES;
}

__global__ void k_fill(const int* __restrict__ ei, const int* __restrict__ indptr,
                       int* cursor, int* srcs) {
    int e = blockIdx.x * blockDim.x + threadIdx.x;
    if (e >= N_EDGES) return;
    int d = ei[N_EDGES + e];
    int pos = indptr[d] + atomicAdd(&cursor[d], 1);
    srcs[pos] = ei[e];
}

// ================= gather aggregation, 128 channels =================
// one warp per dst node; optional fused bias (+relu)
__global__ void k_gather128(const float* __restrict__ H, float* __restrict__ OUT,
                            const int* __restrict__ indptr, const int* __restrict__ srcs,
                            const float* __restrict__ dinv,
                            const float* __restrict__ bias, int do_relu) {
    int gt = blockIdx.x * blockDim.x + threadIdx.x;
    int n = gt >> 5;
    int lane = gt & 31;
    if (n >= N_NODES) return;
    const float4* Hv = (const float4*)H;
    float dn = dinv[n];
    float s0 = dn * dn;
    float4 acc = Hv[n * 32 + lane];
    acc.x *= s0; acc.y *= s0; acc.z *= s0; acc.w *= s0;
    int j = indptr[n], end = indptr[n + 1];
    for (; j + 1 < end; j += 2) {
        int s1 = srcs[j], s2 = srcs[j + 1];
        float n1 = dinv[s1] * dn, n2 = dinv[s2] * dn;
        float4 v1 = Hv[s1 * 32 + lane];
        float4 v2 = Hv[s2 * 32 + lane];
        acc.x += v1.x * n1 + v2.x * n2;
        acc.y += v1.y * n1 + v2.y * n2;
        acc.z += v1.z * n1 + v2.z * n2;
        acc.w += v1.w * n1 + v2.w * n2;
    }
    if (j < end) {
        int s1 = srcs[j];
        float n1 = dinv[s1] * dn;
        float4 v1 = Hv[s1 * 32 + lane];
        acc.x += v1.x * n1; acc.y += v1.y * n1;
        acc.z += v1.z * n1; acc.w += v1.w * n1;
    }
    if (bias) {
        float4 b = ((const float4*)bias)[lane];
        acc.x += b.x; acc.y += b.y; acc.z += b.z; acc.w += b.w;
    }
    if (do_relu) {
        acc.x = fmaxf(acc.x, 0.f); acc.y = fmaxf(acc.y, 0.f);
        acc.z = fmaxf(acc.z, 0.f); acc.w = fmaxf(acc.w, 0.f);
    }
    ((float4*)OUT)[n * 32 + lane] = acc;
}

// ================= SGEMM with packed f32x2 FMA =================
// C[M,N] = A[M,K] @ B[K,N] (+bias, relu). BM=BN=128, BK=8, 256 threads, 8x8/thread.
typedef unsigned long long ull;

__device__ __forceinline__ ull pack2(float lo, float hi) {
    ull r;
    asm("mov.b64 %0, {%1, %2};" : "=l"(r) : "r"(__float_as_uint(lo)), "r"(__float_as_uint(hi)));
    return r;
}
__device__ __forceinline__ void unpack2(ull v, float& lo, float& hi) {
    unsigned a, b;
    asm("mov.b64 {%0, %1}, %2;" : "=r"(a), "=r"(b) : "l"(v));
    lo = __uint_as_float(a); hi = __uint_as_float(b);
}
__device__ __forceinline__ void fma2(ull& d, ull a, ull b) {
    asm("fma.rn.f32x2 %0, %1, %2, %0;" : "+l"(d) : "l"(a), "l"(b));
}

__global__ __launch_bounds__(256) void k_sgemm2(const float* __restrict__ A,
                                                const float* __restrict__ B,
                                                float* __restrict__ C,
                                                int M, int K, int N,
                                                const float* __restrict__ bias,
                                                int do_relu) {
    __shared__ __align__(16) float As[8][128];  // [k][row]
    __shared__ __align__(16) float Bs[8][128];  // [k][col]

    int tid = threadIdx.x;
    int tx = tid & 15;         // 0..15 col octs
    int ty = tid >> 4;         // 0..15 row octs
    int rowBase = blockIdx.y * 128;
    int colBase = blockIdx.x * 128;

    int arow = tid >> 1;            // 0..127
    int ak   = (tid & 1) * 4;       // 0 or 4
    int brow = tid >> 5;            // 0..7
    int bcol = (tid & 31) * 4;      // 0..124

    ull acc[4][8];                  // [row-pair][col] packed (r2i, r2i+1)
#pragma unroll
    for (int i = 0; i < 4; i++)
#pragma unroll
        for (int j = 0; j < 8; j++) acc[i][j] = 0ull;

    for (int k0 = 0; k0 < K; k0 += 8) {
        int gr = rowBase + arow;
        float4 av = make_float4(0.f, 0.f, 0.f, 0.f);
        if (gr < M) av = *(const float4*)(A + (size_t)gr * K + k0 + ak);
        As[ak + 0][arow] = av.x;
        As[ak + 1][arow] = av.y;
        As[ak + 2][arow] = av.z;
        As[ak + 3][arow] = av.w;

        float4 bv = *(const float4*)(B + (size_t)(k0 + brow) * N + colBase + bcol);
        *(float4*)&Bs[brow][bcol] = bv;
        __syncthreads();

#pragma unroll
        for (int kk = 0; kk < 8; kk++) {
            ulonglong2 a01 = *(const ulonglong2*)&As[kk][ty * 8];       // rows (0,1),(2,3)
            ulonglong2 a23 = *(const ulonglong2*)&As[kk][ty * 8 + 4];   // rows (4,5),(6,7)
            float4 b0 = *(const float4*)&Bs[kk][tx * 8];
            float4 b1 = *(const float4*)&Bs[kk][tx * 8 + 4];
            ull ap[4] = {a01.x, a01.y, a23.x, a23.y};
            ull bd[8];
            bd[0] = pack2(b0.x, b0.x); bd[1] = pack2(b0.y, b0.y);
            bd[2] = pack2(b0.z, b0.z); bd[3] = pack2(b0.w, b0.w);
            bd[4] = pack2(b1.x, b1.x); bd[5] = pack2(b1.y, b1.y);
            bd[6] = pack2(b1.z, b1.z); bd[7] = pack2(b1.w, b1.w);
#pragma unroll
            for (int i = 0; i < 4; i++)
#pragma unroll
                for (int j = 0; j < 8; j++) fma2(acc[i][j], ap[i], bd[j]);
        }
        __syncthreads();
    }

    // epilogue
#pragma unroll
    for (int i = 0; i < 4; i++) {
        float lo[8], hi[8];
#pragma unroll
        for (int j = 0; j < 8; j++) unpack2(acc[i][j], lo[j], hi[j]);
#pragma unroll
        for (int p = 0; p < 2; p++) {
            int row = rowBase + ty * 8 + 2 * i + p;
            if (row >= M) continue;
            float* src = p ? hi : lo;
            float o[8];
#pragma unroll
            for (int j = 0; j < 8; j++) {
                float v = src[j];
                if (bias) v += bias[colBase + tx * 8 + j];
                if (do_relu) v = fmaxf(v, 0.f);
                o[j] = v;
            }
            float* outp = C + (size_t)row * N + colBase + tx * 8;
            *(float4*)(outp) = make_float4(o[0], o[1], o[2], o[3]);
            *(float4*)(outp + 4) = make_float4(o[4], o[5], o[6], o[7]);
        }
    }
}

// ================= layer 3 =================
__global__ void k_gemm_small(const float* __restrict__ H2, const float* __restrict__ W3,
                             float* __restrict__ H3) {
    __shared__ float w[256];
    if (threadIdx.x < 256) w[threadIdx.x] = W3[threadIdx.x];
    __syncthreads();
    int r = blockIdx.x * blockDim.x + threadIdx.x;
    if (r >= N_NODES) return;
    float a0 = 0.f, a1 = 0.f;
    const float4* row = (const float4*)(H2 + (size_t)r * 128);
#pragma unroll
    for (int k = 0; k < 32; k++) {
        float4 v = row[k];
        int b = k * 8;
        a0 += v.x * w[b + 0] + v.y * w[b + 2] + v.z * w[b + 4] + v.w * w[b + 6];
        a1 += v.x * w[b + 1] + v.y * w[b + 3] + v.z * w[b + 5] + v.w * w[b + 7];
    }
    H3[(size_t)r * 2 + 0] = a0;
    H3[(size_t)r * 2 + 1] = a1;
}

// gather 2ch + bias + log_softmax, one thread per node
__global__ void k_gather2_lsm(const float* __restrict__ H3, float* __restrict__ OUT,
                              const int* __restrict__ indptr, const int* __restrict__ srcs,
                              const float* __restrict__ dinv, const float* __restrict__ b3) {
    int n = blockIdx.x * blockDim.x + threadIdx.x;
    if (n >= N_NODES) return;
    float dn = dinv[n];
    float s0 = dn * dn;
    float2 h = *(const float2*)(H3 + (size_t)n * 2);
    float a0 = h.x * s0, a1 = h.y * s0;
    int end = indptr[n + 1];
    for (int j = indptr[n]; j < end; j++) {
        int s = srcs[j];
        float nrm = dinv[s] * dn;
        float2 v = *(const float2*)(H3 + (size_t)s * 2);
        a0 += v.x * nrm;
        a1 += v.y * nrm;
    }
    float v0 = a0 + b3[0];
    float v1 = a1 + b3[1];
    float m = fmaxf(v0, v1);
    float lse = m + logf(expf(v0 - m) + expf(v1 - m));
    OUT[(size_t)n * 2 + 0] = v0 - lse;
    OUT[(size_t)n * 2 + 1] = v1 - lse;
}

// ---------------- launch ----------------
extern "C" void kernel_launch(void* const* d_in, const int* in_sizes, int n_in,
                              void* d_out, int out_size) {
    const float* x  = (const float*)d_in[0];
    const float* W1 = (const float*)d_in[1];
    const float* b1 = (const float*)d_in[2];
    const float* W2 = (const float*)d_in[3];
    const float* b2 = (const float*)d_in[4];
    const float* W3 = (const float*)d_in[5];
    const float* b3 = (const float*)d_in[6];
    const int*   ei = (const int*)d_in[7];   // int32 (JAX x64 disabled)
    float* out = (float*)d_out;

    float *B1, *B2, *dinv;
    int *indptr, *cursor, *srcs, *blocksums;
    cudaGetSymbolAddress((void**)&B1, g_B1);
    cudaGetSymbolAddress((void**)&B2, g_B2);
    cudaGetSymbolAddress((void**)&dinv, g_dinv);
    cudaGetSymbolAddress((void**)&indptr, g_indptr);
    cudaGetSymbolAddress((void**)&cursor, g_cursor);
    cudaGetSymbolAddress((void**)&srcs, g_srcs);
    cudaGetSymbolAddress((void**)&blocksums, g_blocksums);

    const int N = N_NODES, E = N_EDGES, TB = 256;
    const int nScanBlocks = (N + 511) / 512;  // 98

    // ---- CSR build + dinv ----
    k_zero <<<(N + TB - 1) / TB, TB>>>(cursor);
    k_count<<<(E + TB - 1) / TB, TB>>>(cursor, ei);
    k_scan1<<<nScanBlocks, 512>>>(cursor, indptr, blocksums, dinv);
    k_scan2<<<1, 128>>>(blocksums, nScanBlocks);
    k_scan3<<<(N + TB - 1) / TB, TB>>>(indptr, blocksums, cursor);
    k_fill <<<(E + TB - 1) / TB, TB>>>(ei, indptr, cursor, srcs);

    // ---- layer 1: agg(x) -> B1; relu((A x)@W1 + b1) -> B2 ----
    k_gather128<<<(N * 32 + TB - 1) / TB, TB>>>(x, B1, indptr, srcs, dinv, nullptr, 0);
    {
        dim3 g(256 / 128, (N + 127) / 128);
        k_sgemm2<<<g, 256>>>(B1, W1, B2, N, 128, 256, b1, 1);
    }

    // ---- layer 2: h1@W2 -> B1; relu(agg + b2) -> B2 ----
    {
        dim3 g(128 / 128, (N + 127) / 128);
        k_sgemm2<<<g, 256>>>(B2, W2, B1, N, 256, 128, nullptr, 0);
    }
    k_gather128<<<(N * 32 + TB - 1) / TB, TB>>>(B1, B2, indptr, srcs, dinv, b2, 1);

    // ---- layer 3: h2@W3 -> B1[:, :2]; agg + b3 + log_softmax -> out ----
    k_gemm_small<<<(N + TB - 1) / TB, TB>>>(B2, W3, B1);
    k_gather2_lsm<<<(N + TB - 1) / TB, TB>>>(B1, out, indptr, srcs, dinv, b3);
}